// round 10
// baseline (speedup 1.0000x reference)
#include <cuda_runtime.h>
#include <cstddef>

#define Bc 16
#define Fc 4
#define Kc 16
#define KH 8
#define Yc 16
#define Xc 16
#define Pc 16
#define Tc 8
#define NT 256
#define NGROUP 128            // (b,f,kh) groups
#define YBLK 8                // blocks per group (2 y-rows each)

typedef unsigned long long u64;

__device__ float g_partial[NGROUP * YBLK * KH];
__device__ int   g_cnt[NGROUP];        // zero-init; self-resetting

__device__ __forceinline__ u64 pk2(float lo, float hi) {
    u64 r; asm("mov.b64 %0, {%1,%2};" : "=l"(r) : "f"(lo), "f"(hi)); return r;
}
__device__ __forceinline__ void unpk2(u64 v, float& lo, float& hi) {
    asm("mov.b64 {%0,%1}, %2;" : "=f"(lo), "=f"(hi) : "l"(v));
}
__device__ __forceinline__ u64 fma2_(u64 a, u64 b, u64 c) {
    u64 d; asm("fma.rn.f32x2 %0, %1, %2, %3;" : "=l"(d) : "l"(a), "l"(b), "l"(c)); return d;
}
__device__ __forceinline__ u64 mul2_(u64 a, u64 b) {
    u64 d; asm("mul.rn.f32x2 %0, %1, %2;" : "=l"(d) : "l"(a), "l"(b)); return d;
}

// Block = (group g=(b,f,kh), yq). 256 threads = (x,p), 2 y-rows per thread.
// Blocks write 8-k partials; the 8th-arriving block of each group computes
// the batch means + normalization integral, combines partials in fixed y
// order (deterministic), scales, stores, and resets the group counter.
__global__ void __launch_bounds__(NT) pkl_main(
    const float* __restrict__ field, const float* __restrict__ darea,
    const float* __restrict__ dlev,  const float* __restrict__ dtime,
    const float* __restrict__ lat_mean, const float* __restrict__ lat_logstd,
    const float* __restrict__ lon_mean, const float* __restrict__ lon_logstd,
    const float* __restrict__ lev_mean, const float* __restrict__ lev_logstd,
    const float* __restrict__ time_logtau, float* __restrict__ out)
{
    int blk = blockIdx.x;
    int yq = blk & 7;
    int g  = blk >> 3;
    int kh = g & 1;
    int f  = (g >> 1) & 3;
    int b  = g >> 3;
    int tid  = threadIdx.x;
    int lane = tid & 31;
    int warp = tid >> 5;
    int p = tid & 15;
    int x = tid >> 4;
    int y0 = yq * 2;

    // ---- field loads first (2 rows x 2 float4, MLP=4) ----
    const float4* src = (const float4*)(field
        + (size_t)(b * Fc + f) * (Yc * Xc * Pc * Tc)
        + (y0 * Xc * Pc + x * Pc + p) * Tc);
    float4 R[2][2];
    R[0][0] = src[0];   R[0][1] = src[1];
    R[1][0] = src[512]; R[1][1] = src[513];   // y-stride = 2048 floats

    __shared__ __align__(16) float sklat[Yc][KH];
    __shared__ __align__(16) float sklon[Xc][KH];
    __shared__ __align__(16) float sklev[Pc][KH];
    __shared__ float srate[KH];
    __shared__ float sda2[2 * Xc];       // this block's darea rows
    __shared__ float sdl[Pc], sdt[Tc];
    __shared__ float sred[8][KH];
    __shared__ float sdlm[Pc], sdtm[Tc];
    __shared__ int sLast;

    // ---- setup: 1D kernels + own-sample quadrature (light) ----
    for (int idx = tid; idx < 3 * 16 * KH; idx += NT) {
        int j   = idx & 7;
        int d   = (idx >> 3) & 15;
        int dim = idx >> 7;
        int fk  = f * Kc + kh * KH + j;
        float coord = -1.0f + 2.0f * (float)d / 15.0f;
        float m, ls;
        if (dim == 0)      { m = lat_mean[fk]; ls = lat_logstd[fk]; }
        else if (dim == 1) { m = lon_mean[fk]; ls = lon_logstd[fk]; }
        else               { m = lev_mean[fk]; ls = lev_logstd[fk]; }
        float z = (coord - m) * expf(-ls);
        float gg = expf(-0.5f * z * z);
        if (dim == 0)      sklat[d][j] = gg;
        else if (dim == 1) sklon[d][j] = gg;
        else               sklev[d][j] = gg;
    }
    if (tid >= 248) {
        int j = tid - 248;
        int fk = f * Kc + kh * KH + j;
        float tau = expf(time_logtau[fk]) + 1e-4f;
        srate[j] = expf(-1.0f / tau);      // ktime[t] = r^t
    }
    if (tid < 32)
        sda2[tid] = darea[b * 256 + (y0 + (tid >> 4)) * 16 + (tid & 15)];
    if (tid >= 32 && tid < 48) sdl[tid - 32] = dlev[b * Pc + (tid - 32)];
    if (tid >= 48 && tid < 56) sdt[tid - 48] = dtime[b * Tc + (tid - 48)];
    __syncthreads();

    // ---- main contraction (R3 inner body, 2 rows) ----
    u64 rate2[4];
    #pragma unroll
    for (int jj = 0; jj < 4; jj++)
        rate2[jj] = pk2(srate[2 * jj], srate[2 * jj + 1]);
    float dtr[Tc];
    #pragma unroll
    for (int t = 0; t < Tc; t++) dtr[t] = sdt[t];
    u64 acc[4];
    #pragma unroll
    for (int jj = 0; jj < 4; jj++) acc[jj] = pk2(0.f, 0.f);

    #pragma unroll
    for (int yy = 0; yy < 2; yy++) {
        int y = y0 + yy;
        float4 a0 = R[yy][0], a1 = R[yy][1];
        float ft0 = a0.x * dtr[0], ft1 = a0.y * dtr[1];
        float ft2 = a0.z * dtr[2], ft3 = a0.w * dtr[3];
        float ft4 = a1.x * dtr[4], ft5 = a1.y * dtr[5];
        float ft6 = a1.z * dtr[6], ft7 = a1.w * dtr[7];
        u64 fb[8];
        fb[0] = pk2(ft0, ft0); fb[1] = pk2(ft1, ft1);
        fb[2] = pk2(ft2, ft2); fb[3] = pk2(ft3, ft3);
        fb[4] = pk2(ft4, ft4); fb[5] = pk2(ft5, ft5);
        fb[6] = pk2(ft6, ft6); fb[7] = pk2(ft7, ft7);
        float dav = sda2[yy * 16 + x];
        u64 da2p = pk2(dav, dav);
        const u64* klrow = (const u64*)&sklat[y][0];
        #pragma unroll
        for (int jj = 0; jj < 4; jj++) {
            u64 wy = mul2_(klrow[jj], da2p);
            u64 dd = fb[7];
            #pragma unroll
            for (int t = 6; t >= 0; t--) dd = fma2_(dd, rate2[jj], fb[t]);
            acc[jj] = fma2_(wy, dd, acc[jj]);
        }
    }

    float dlp = sdl[p];
    float av[KH];
    #pragma unroll
    for (int jj = 0; jj < 4; jj++) {
        u64 pre = pk2(sklon[x][2 * jj]     * sklev[p][2 * jj]     * dlp,
                      sklon[x][2 * jj + 1] * sklev[p][2 * jj + 1] * dlp);
        u64 r = mul2_(pre, acc[jj]);
        unpk2(r, av[2 * jj], av[2 * jj + 1]);
    }
    #pragma unroll
    for (int j = 0; j < KH; j++) {
        float v = av[j];
        #pragma unroll
        for (int o = 16; o > 0; o >>= 1) v += __shfl_xor_sync(0xFFFFFFFFu, v, o);
        if (lane == 0) sred[warp][j] = v;
    }
    __syncthreads();

    // ---- publish partials, detect last block of group ----
    if (tid < KH) {
        float s = 0.f;
        #pragma unroll
        for (int w = 0; w < 8; w++) s += sred[w][tid];
        g_partial[blk * KH + tid] = s;
    }
    __threadfence();
    __syncthreads();
    if (tid == 0) {
        int old = atomicAdd(&g_cnt[g], 1);
        sLast = (old == YBLK - 1) ? 1 : 0;
    }
    __syncthreads();
    if (!sLast) return;

    // ================= finisher (one block per group) =================
    __threadfence();   // acquire: other blocks' partials now visible

    // batch means + integral partials (sred reused)
    {
        float s = 0.f;
        #pragma unroll
        for (int bb = 0; bb < Bc; bb++) s += darea[bb * 256 + tid];
        float dm = s * (1.f / 16.f);
        int yi = tid >> 4, xi = tid & 15;
        #pragma unroll
        for (int j = 0; j < KH; j++) {
            float v = dm * sklat[yi][j] * sklon[xi][j];
            #pragma unroll
            for (int o = 16; o > 0; o >>= 1) v += __shfl_xor_sync(0xFFFFFFFFu, v, o);
            if (lane == 0) sred[warp][j] = v;
        }
    }
    if (tid < Pc) {
        float s = 0.f;
        #pragma unroll
        for (int bb = 0; bb < Bc; bb++) s += dlev[bb * Pc + tid];
        sdlm[tid] = s * (1.f / 16.f);
    }
    if (tid >= 32 && tid < 32 + Tc) {
        int i = tid - 32;
        float s = 0.f;
        #pragma unroll
        for (int bb = 0; bb < Bc; bb++) s += dtime[bb * Tc + i];
        sdtm[i] = s * (1.f / 16.f);
    }
    __syncthreads();

    if (tid < KH) {
        float Syx = 0.f;
        #pragma unroll
        for (int w = 0; w < 8; w++) Syx += sred[w][tid];
        float Sp = 0.f;
        #pragma unroll
        for (int pp = 0; pp < Pc; pp++) Sp = fmaf(sklev[pp][tid], sdlm[pp], Sp);
        float r = srate[tid];
        float St = sdtm[Tc - 1];
        #pragma unroll
        for (int t = Tc - 2; t >= 0; t--) St = fmaf(St, r, sdtm[t]);
        float winv = 1.0f / (Syx * Sp * St + 1e-4f);

        float s = 0.f;                      // fixed y order -> deterministic
        #pragma unroll
        for (int q = 0; q < YBLK; q++) s += g_partial[(g * YBLK + q) * KH + tid];
        out[b * (Fc * Kc) + f * Kc + kh * KH + tid] = s * winv;
    }
    if (tid == 0) g_cnt[g] = 0;            // reset for next launch/replay
}

extern "C" void kernel_launch(void* const* d_in, const int* in_sizes, int n_in,
                              void* d_out, int out_size)
{
    pkl_main<<<NGROUP * YBLK, NT>>>(
        (const float*)d_in[0], (const float*)d_in[1],
        (const float*)d_in[2], (const float*)d_in[3],
        (const float*)d_in[4], (const float*)d_in[5],
        (const float*)d_in[6], (const float*)d_in[7],
        (const float*)d_in[8], (const float*)d_in[9],
        (const float*)d_in[10], (float*)d_out);
}

// round 12
// speedup vs baseline: 1.3642x; 1.3642x over previous
#include <cuda_runtime.h>
#include <cstddef>

#define Bc 16
#define Fc 4
#define Kc 16
#define KQ 4          // k's per block (k-quarter)
#define Yc 16
#define Xc 16
#define Pc 16
#define Tc 8
#define NT 512

typedef unsigned long long u64;

// sm_103a packed f32x2 ops (PTX-only)
__device__ __forceinline__ u64 pk2(float lo, float hi) {
    u64 r; asm("mov.b64 %0, {%1,%2};" : "=l"(r) : "f"(lo), "f"(hi)); return r;
}
__device__ __forceinline__ void unpk2(u64 v, float& lo, float& hi) {
    asm("mov.b64 {%0,%1}, %2;" : "=f"(lo), "=f"(hi) : "l"(v));
}
__device__ __forceinline__ u64 fma2_(u64 a, u64 b, u64 c) {
    u64 d; asm("fma.rn.f32x2 %0, %1, %2, %3;" : "=l"(d) : "l"(a), "l"(b), "l"(c)); return d;
}
__device__ __forceinline__ u64 mul2_(u64 a, u64 b) {
    u64 d; asm("mul.rn.f32x2 %0, %1, %2;" : "=l"(d) : "l"(a), "l"(b)); return d;
}

// Block = (b, f, kq): 4 k's per block, grid 256 (one wave, 2 blocks/SM).
// 512 threads = (yh:1b, x:4b, p:4b); each thread contracts 8 y-rows.
// Row math: q_i = (f_{2i},f_{2i+1}) * (dt_{2i},dt_{2i+1})  [(even,odd) t lanes],
// Horner in r^2, weight = (klat*darea) pair from an 8KB LDS table; the odd-lane
// r-correction and (klon*klev*dlev) factor are applied once after the loop.
// NOTE: barrier 2 fences the cross-warp-read sklatda2/sint tables (R11 bug).
__global__ void __launch_bounds__(NT, 2) pkl_fused(
    const float* __restrict__ field, const float* __restrict__ darea,
    const float* __restrict__ dlev,  const float* __restrict__ dtime,
    const float* __restrict__ lat_mean, const float* __restrict__ lat_logstd,
    const float* __restrict__ lon_mean, const float* __restrict__ lon_logstd,
    const float* __restrict__ lev_mean, const float* __restrict__ lev_logstd,
    const float* __restrict__ time_logtau, float* __restrict__ out)
{
    int blk = blockIdx.x;
    int kq = blk & 3;
    int f  = (blk >> 2) & 3;
    int b  = blk >> 4;
    int tid  = threadIdx.x;
    int lane = tid & 31;
    int warp = tid >> 5;
    int p  = tid & 15;
    int x  = (tid >> 4) & 15;
    int yh = tid >> 8;                     // 0 or 1
    int y0 = yh * 8;

    __shared__ __align__(16) float sklat[Yc][KQ];
    __shared__ __align__(16) float sklon[Xc][KQ];
    __shared__ __align__(16) float sklev[Pc][KQ];
    __shared__ __align__(16) u64 sklatda2[Yc * Xc * KQ];  // (klat*da, klat*da)
    __shared__ __align__(16) float sdt[Tc];               // u64-pair readable
    __shared__ float srate[KQ], sr2[KQ];
    __shared__ float sdamean[Yc * Xc], sda[Yc * Xc];
    __shared__ float sdl[Pc], sdlm[Pc], sdtm[Tc];
    __shared__ float sred[16][KQ];
    __shared__ float sint[8][KQ];          // per-warp partial Syx

    // ================= phase 1: params + quadrature =================
    if (tid < 3 * 16 * KQ) {               // 192 gaussians for this block's 4 k's
        int j   = tid & 3;
        int d   = (tid >> 2) & 15;
        int dim = tid >> 6;
        int fk  = f * Kc + kq * KQ + j;
        float coord = -1.0f + 2.0f * (float)d / 15.0f;
        float m, ls;
        if (dim == 0)      { m = lat_mean[fk]; ls = lat_logstd[fk]; }
        else if (dim == 1) { m = lon_mean[fk]; ls = lon_logstd[fk]; }
        else               { m = lev_mean[fk]; ls = lev_logstd[fk]; }
        float z = (coord - m) * expf(-ls);
        float g = expf(-0.5f * z * z);
        if (dim == 0)      sklat[d][j] = g;
        else if (dim == 1) sklon[d][j] = g;
        else               sklev[d][j] = g;
    }
    if (tid >= 192 && tid < 192 + KQ) {
        int j = tid - 192;
        int fk = f * Kc + kq * KQ + j;
        float tau = expf(time_logtau[fk]) + 1e-4f;
        float r = expf(-1.0f / tau);       // ktime[t] = r^t
        srate[j] = r;
        sr2[j] = r * r;
    }
    if (tid >= 208 && tid < 208 + Pc) {
        int i = tid - 208;
        float s = 0.f;
        #pragma unroll
        for (int bb = 0; bb < Bc; bb++) s += dlev[bb * Pc + i];
        sdlm[i] = s * (1.f / 16.f);
        sdl[i] = dlev[b * Pc + i];
    }
    if (tid >= 224 && tid < 224 + Tc) {
        int i = tid - 224;
        float s = 0.f;
        #pragma unroll
        for (int bb = 0; bb < Bc; bb++) s += dtime[bb * Tc + i];
        sdtm[i] = s * (1.f / 16.f);
        sdt[i] = dtime[b * Tc + i];
    }
    if (tid >= 256) {
        int i = tid - 256;
        float s = 0.f;
        #pragma unroll
        for (int bb = 0; bb < Bc; bb++) s += darea[bb * 256 + i];
        sdamean[i] = s * (1.f / 16.f);
        sda[i] = darea[b * 256 + i];
    }
    __syncthreads();   // ---- barrier 1 ----

    // ---- (klat*darea) pair table: 1024 entries, 2 per thread ----
    #pragma unroll
    for (int rep = 0; rep < 2; rep++) {
        int i = tid + rep * 512;
        int k  = i & 3;
        int yx = i >> 2;
        float v = sklat[yx >> 4][k] * sda[yx];
        sklatda2[i] = pk2(v, v);
    }

    // ---- integral partials (warps 0-7; consumed after barrier 3) ----
    if (warp < 8) {
        int yi = tid >> 4, xi = tid & 15;  // tid < 256 here
        float dm = sdamean[tid];
        #pragma unroll
        for (int j = 0; j < KQ; j++) {
            float v = dm * sklat[yi][j] * sklon[xi][j];
            #pragma unroll
            for (int o = 16; o > 0; o >>= 1) v += __shfl_xor_sync(0xFFFFFFFFu, v, o);
            if (lane == 0) sint[warp][j] = v;
        }
    }
    __syncthreads();   // ---- barrier 2: fence sklatda2 before cross-warp reads

    // ================= main contraction: 8 rows, depth-3 prefetch ==========
    u64 dt2[4];
    {
        const u64* sdt64 = (const u64*)sdt;      // (dt0,dt1)(dt2,dt3)...
        dt2[0] = sdt64[0]; dt2[1] = sdt64[1];
        dt2[2] = sdt64[2]; dt2[3] = sdt64[3];
    }
    u64 ss2k[KQ];
    #pragma unroll
    for (int k = 0; k < KQ; k++) { float v = sr2[k]; ss2k[k] = pk2(v, v); }
    u64 acc[KQ];
    #pragma unroll
    for (int k = 0; k < KQ; k++) acc[k] = pk2(0.f, 0.f);

    const ulonglong2* src = (const ulonglong2*)(field
        + (size_t)(b * Fc + f) * (Yc * Xc * Pc * Tc)
        + (y0 * Xc * Pc + x * Pc + p) * Tc);
    // y-stride = 2048 floats = 512 ulonglong2

    ulonglong2 R[3][2];
    R[0][0] = src[0];    R[0][1] = src[1];
    R[1][0] = src[512];  R[1][1] = src[513];
    R[2][0] = src[1024]; R[2][1] = src[1025];

    #pragma unroll
    for (int yy = 0; yy < 8; yy++) {
        int s = yy % 3;
        ulonglong2 a0 = R[s][0], a1 = R[s][1];
        if (yy < 5) {
            R[s][0] = src[(yy + 3) * 512];
            R[s][1] = src[(yy + 3) * 512 + 1];
        }
        int y = y0 + yy;
        u64 q0 = mul2_(a0.x, dt2[0]);
        u64 q1 = mul2_(a0.y, dt2[1]);
        u64 q2 = mul2_(a1.x, dt2[2]);
        u64 q3 = mul2_(a1.y, dt2[3]);
        const u64* w = &sklatda2[(y << 6) + (x << 2)];
        #pragma unroll
        for (int k = 0; k < KQ; k++) {
            u64 d = fma2_(q3, ss2k[k], q2);    // Horner in r^2, lanes (E,O)
            d = fma2_(d, ss2k[k], q1);
            d = fma2_(d, ss2k[k], q0);
            acc[k] = fma2_(w[k], d, acc[k]);   // (klat*darea) pair
        }
    }

    // deferred odd-lane correction + (x,p)-dependent factors
    float dlp = sdl[p];
    float av[KQ];
    #pragma unroll
    for (int k = 0; k < KQ; k++) {
        float E, O;
        unpk2(acc[k], E, O);
        float dot = fmaf(srate[k], O, E);
        av[k] = dot * (sklon[x][k] * sklev[p][k] * dlp);
    }

    // ---- deterministic block reduction ----
    #pragma unroll
    for (int j = 0; j < KQ; j++) {
        float v = av[j];
        #pragma unroll
        for (int o = 16; o > 0; o >>= 1) v += __shfl_xor_sync(0xFFFFFFFFu, v, o);
        if (lane == 0) sred[warp][j] = v;
    }
    __syncthreads();   // ---- barrier 3 ----

    // ---- finalize: Syx/Sp/St -> winv, scale, store (4 threads) ----
    if (tid < KQ) {
        float s = 0.f;
        #pragma unroll
        for (int w = 0; w < 16; w++) s += sred[w][tid];
        float Syx = 0.f;
        #pragma unroll
        for (int w = 0; w < 8; w++) Syx += sint[w][tid];
        float Sp = 0.f;
        #pragma unroll
        for (int pp = 0; pp < Pc; pp++) Sp = fmaf(sklev[pp][tid], sdlm[pp], Sp);
        float r = srate[tid];
        float St = sdtm[Tc - 1];
        #pragma unroll
        for (int t = Tc - 2; t >= 0; t--) St = fmaf(St, r, sdtm[t]);
        float winv = 1.0f / (Syx * Sp * St + 1e-4f);
        out[b * (Fc * Kc) + f * Kc + kq * KQ + tid] = s * winv;
    }
}

extern "C" void kernel_launch(void* const* d_in, const int* in_sizes, int n_in,
                              void* d_out, int out_size)
{
    pkl_fused<<<Bc * Fc * KQ, NT>>>(
        (const float*)d_in[0], (const float*)d_in[1],
        (const float*)d_in[2], (const float*)d_in[3],
        (const float*)d_in[4], (const float*)d_in[5],
        (const float*)d_in[6], (const float*)d_in[7],
        (const float*)d_in[8], (const float*)d_in[9],
        (const float*)d_in[10], (float*)d_out);
}

// round 13
// speedup vs baseline: 1.6863x; 1.2362x over previous
#include <cuda_runtime.h>
#include <cstddef>

#define Bc 16
#define Fc 4
#define Kc 16
#define KH 8          // k's per block (k-half)
#define Yc 16
#define Xc 16
#define Pc 16
#define Tc 8
#define NT 1024

typedef unsigned long long u64;

// sm_103a packed f32x2 ops (PTX-only; ptxas never auto-fuses these)
__device__ __forceinline__ u64 pk2(float lo, float hi) {
    u64 r; asm("mov.b64 %0, {%1,%2};" : "=l"(r) : "f"(lo), "f"(hi)); return r;
}
__device__ __forceinline__ void unpk2(u64 v, float& lo, float& hi) {
    asm("mov.b64 {%0,%1}, %2;" : "=f"(lo), "=f"(hi) : "l"(v));
}
__device__ __forceinline__ u64 fma2_(u64 a, u64 b, u64 c) {
    u64 d; asm("fma.rn.f32x2 %0, %1, %2, %3;" : "=l"(d) : "l"(a), "l"(b), "l"(c)); return d;
}
__device__ __forceinline__ u64 mul2_(u64 a, u64 b) {
    u64 d; asm("mul.rn.f32x2 %0, %1, %2;" : "=l"(d) : "l"(a), "l"(b)); return d;
}

// One block = (b, f, k-half). 1024 threads: thread = (yh:2b, x:4b, p:4b),
// each thread contracts 4 y-rows (8 t-values each) for 8 k's.
__global__ void __launch_bounds__(NT, 1) pkl_fused(
    const float* __restrict__ field, const float* __restrict__ darea,
    const float* __restrict__ dlev,  const float* __restrict__ dtime,
    const float* __restrict__ lat_mean, const float* __restrict__ lat_logstd,
    const float* __restrict__ lon_mean, const float* __restrict__ lon_logstd,
    const float* __restrict__ lev_mean, const float* __restrict__ lev_logstd,
    const float* __restrict__ time_logtau, float* __restrict__ out)
{
    int blk = blockIdx.x;
    int kh = blk & 1;
    int f  = (blk >> 1) & 3;
    int b  = blk >> 3;
    int tid  = threadIdx.x;
    int lane = tid & 31;
    int warp = tid >> 5;

    __shared__ __align__(16) float sklat[Yc][KH];
    __shared__ __align__(16) float sklon[Xc][KH];
    __shared__ __align__(16) float sklev[Pc][KH];
    __shared__ float srate[KH], swinv[KH];
    __shared__ float sdamean[Yc * Xc], sda[Yc * Xc];
    __shared__ float sdlmean[Pc], sdl[Pc], sdtm[Tc], sdt[Tc];
    __shared__ float sred[32][KH];

    // ---- 1D parametric kernels for this block's 8 k's (384 gaussians) ----
    if (tid < 3 * 16 * KH) {
        int idx = tid;
        int j   = idx & 7;
        int d   = (idx >> 3) & 15;
        int dim = idx >> 7;
        int fk  = f * Kc + kh * KH + j;
        float coord = -1.0f + 2.0f * (float)d / 15.0f;
        float m, ls;
        if (dim == 0)      { m = lat_mean[fk]; ls = lat_logstd[fk]; }
        else if (dim == 1) { m = lon_mean[fk]; ls = lon_logstd[fk]; }
        else               { m = lev_mean[fk]; ls = lev_logstd[fk]; }
        float z = (coord - m) * expf(-ls);
        float g = expf(-0.5f * z * z);
        if (dim == 0)      sklat[d][j] = g;
        else if (dim == 1) sklon[d][j] = g;
        else               sklev[d][j] = g;
    }
    if (tid >= 512 && tid < 512 + KH) {
        int j = tid - 512;
        int fk = f * Kc + kh * KH + j;
        float tau = expf(time_logtau[fk]) + 1e-4f;
        srate[j] = expf(-1.0f / tau);       // ktime[t] = rate^t
    }
    // ---- batch means + this sample's quadrature weights ----
    if (tid >= 768 && tid < 1024) {
        int i = tid - 768;
        float s = 0.f;
        #pragma unroll
        for (int bb = 0; bb < Bc; bb++) s += darea[bb * 256 + i];
        sdamean[i] = s * (1.f / 16.f);
        sda[i] = darea[b * 256 + i];
    }
    if (tid >= 704 && tid < 704 + Pc) {
        int i = tid - 704;
        float s = 0.f;
        #pragma unroll
        for (int bb = 0; bb < Bc; bb++) s += dlev[bb * Pc + i];
        sdlmean[i] = s * (1.f / 16.f);
        sdl[i] = dlev[b * Pc + i];
    }
    if (tid >= 736 && tid < 736 + Tc) {
        int i = tid - 736;
        float s = 0.f;
        #pragma unroll
        for (int bb = 0; bb < Bc; bb++) s += dtime[bb * Tc + i];
        sdtm[i] = s * (1.f / 16.f);
        sdt[i] = dtime[b * Tc + i];
    }
    __syncthreads();

    // ---- separable normalization integral -> 1/(I + eps) ----
    {
        float c[KH];
        #pragma unroll
        for (int j = 0; j < KH; j++) c[j] = 0.f;
        if (tid < 256) {
            int yi = tid >> 4, xi = tid & 15;
            float dm = sdamean[tid];
            #pragma unroll
            for (int j = 0; j < KH; j++) c[j] = dm * sklat[yi][j] * sklon[xi][j];
        }
        if (warp < 8) {
            #pragma unroll
            for (int j = 0; j < KH; j++) {
                float v = c[j];
                #pragma unroll
                for (int o = 16; o > 0; o >>= 1) v += __shfl_xor_sync(0xFFFFFFFFu, v, o);
                if (lane == 0) sred[warp][j] = v;
            }
        }
        __syncthreads();
        if (tid < KH) {
            float Syx = 0.f;
            #pragma unroll
            for (int w = 0; w < 8; w++) Syx += sred[w][tid];
            float Sp = 0.f;
            #pragma unroll
            for (int p = 0; p < Pc; p++) Sp = fmaf(sklev[p][tid], sdlmean[p], Sp);
            float r = srate[tid];
            float St = sdtm[Tc - 1];
            #pragma unroll
            for (int t = Tc - 2; t >= 0; t--) St = fmaf(St, r, sdtm[t]);
            swinv[tid] = 1.0f / (Syx * Sp * St + 1e-4f);
        }
        __syncthreads();   // sred reused below; swinv must be visible
    }

    // ---- main contraction: thread = (yh, x, p); 4 rows of 8 t-values ----
    int p  = tid & 15;
    int x  = (tid >> 4) & 15;
    int yh = tid >> 8;                     // 0..3
    u64 rate2[4];
    #pragma unroll
    for (int jj = 0; jj < 4; jj++) rate2[jj] = pk2(srate[2 * jj], srate[2 * jj + 1]);
    float dtr[Tc];
    #pragma unroll
    for (int t = 0; t < Tc; t++) dtr[t] = sdt[t];
    u64 acc[4];
    #pragma unroll
    for (int jj = 0; jj < 4; jj++) acc[jj] = pk2(0.f, 0.f);

    const float4* src = (const float4*)(field
        + (size_t)(b * Fc + f) * (Yc * Xc * Pc * Tc)
        + ((yh * 4) * Xc * Pc + x * Pc + p) * Tc);
    // y-stride = X*P*T = 2048 floats = 512 float4

    float4 c0 = src[0], c1 = src[1];
    #pragma unroll
    for (int yy = 0; yy < 4; yy++) {
        float4 n0 = c0, n1 = c1;
        if (yy < 3) { n0 = src[(yy + 1) * 512]; n1 = src[(yy + 1) * 512 + 1]; }
        int y = yh * 4 + yy;
        float ft0 = c0.x * dtr[0], ft1 = c0.y * dtr[1];
        float ft2 = c0.z * dtr[2], ft3 = c0.w * dtr[3];
        float ft4 = c1.x * dtr[4], ft5 = c1.y * dtr[5];
        float ft6 = c1.z * dtr[6], ft7 = c1.w * dtr[7];
        u64 fb[8];
        fb[0] = pk2(ft0, ft0); fb[1] = pk2(ft1, ft1);
        fb[2] = pk2(ft2, ft2); fb[3] = pk2(ft3, ft3);
        fb[4] = pk2(ft4, ft4); fb[5] = pk2(ft5, ft5);
        fb[6] = pk2(ft6, ft6); fb[7] = pk2(ft7, ft7);
        float dav = sda[y * 16 + x];
        u64 da2 = pk2(dav, dav);
        const u64* klrow = (const u64*)&sklat[y][0];   // 8B-aligned LDS.64
        #pragma unroll
        for (int jj = 0; jj < 4; jj++) {
            u64 wy = mul2_(klrow[jj], da2);            // klat[y]*darea, k-pair
            u64 dd = fb[7];
            #pragma unroll
            for (int t = 6; t >= 0; t--) dd = fma2_(dd, rate2[jj], fb[t]);
            acc[jj] = fma2_(wy, dd, acc[jj]);
        }
        c0 = n0; c1 = n1;
    }

    // apply the (x,p)-dependent factor once, after the y/t loop
    float dlp = sdl[p];
    float av[KH];
    #pragma unroll
    for (int jj = 0; jj < 4; jj++) {
        u64 pre = pk2(sklon[x][2 * jj]     * sklev[p][2 * jj]     * dlp,
                      sklon[x][2 * jj + 1] * sklev[p][2 * jj + 1] * dlp);
        u64 r = mul2_(pre, acc[jj]);
        unpk2(r, av[2 * jj], av[2 * jj + 1]);
    }

    // ---- deterministic block reduction: shfl + fixed-order shared sum ----
    #pragma unroll
    for (int j = 0; j < KH; j++) {
        float v = av[j];
        #pragma unroll
        for (int o = 16; o > 0; o >>= 1) v += __shfl_xor_sync(0xFFFFFFFFu, v, o);
        if (lane == 0) sred[warp][j] = v;
    }
    __syncthreads();
    if (tid < KH) {
        float s = 0.f;
        #pragma unroll
        for (int w = 0; w < 32; w++) s += sred[w][tid];
        out[b * (Fc * Kc) + f * Kc + kh * KH + tid] = s * swinv[tid];
    }
}

extern "C" void kernel_launch(void* const* d_in, const int* in_sizes, int n_in,
                              void* d_out, int out_size)
{
    pkl_fused<<<Bc * Fc * 2, NT>>>(
        (const float*)d_in[0], (const float*)d_in[1],
        (const float*)d_in[2], (const float*)d_in[3],
        (const float*)d_in[4], (const float*)d_in[5],
        (const float*)d_in[6], (const float*)d_in[7],
        (const float*)d_in[8], (const float*)d_in[9],
        (const float*)d_in[10], (float*)d_out);
}